// round 1
// baseline (speedup 1.0000x reference)
#include <cuda_runtime.h>
#include <math.h>

// Grid: n=512 (derived at launch from input sizes), nm1=511.
// P = nm1^2 = 261121 plaquettes, E = 2*n*nm1 = 523264 edges, N = n^2 nodes.
#define MAXNM1 511
#define MAXN   (MAXNM1 + 1)
#define MAXP   (MAXNM1 * MAXNM1)
#define MAXE   (2 * MAXN * MAXNM1)

// Static device scratch (no allocations allowed).
__device__ float4 g_M[2][MAXP * 4];     // messages, linear domain, (P,4 slots,2x2) as float4 per slot
__device__ float4 g_phiP[MAXP * 4];     // exp(log_phi_plaq)
__device__ float4 g_phiE[MAXE];         // exp(log_phi_edge)
__device__ double g_F;                  // free-energy accumulator

// ---------------------------------------------------------------------------
// Fast log (Cephes-style, ~1e-7 rel err, FMA-pipe only; input > 0)
// ---------------------------------------------------------------------------
__device__ __forceinline__ float fast_logf(float x) {
    int ix = __float_as_int(x);
    int ex = (ix >> 23) - 127;
    float m = __int_as_float((ix & 0x007FFFFF) | 0x3F800000); // [1,2)
    if (m > 1.41421356f) { m *= 0.5f; ex += 1; }
    float f = m - 1.0f;
    float z = f * f;
    float p = 7.0376836292e-2f;
    p = fmaf(p, f, -1.1514610310e-1f);
    p = fmaf(p, f,  1.1676998740e-1f);
    p = fmaf(p, f, -1.2420140846e-1f);
    p = fmaf(p, f,  1.4249322787e-1f);
    p = fmaf(p, f, -1.6668057665e-1f);
    p = fmaf(p, f,  2.0000714765e-1f);
    p = fmaf(p, f, -2.4999993993e-1f);
    p = fmaf(p, f,  3.3333331174e-1f);
    p = p * z * f;
    p = fmaf(-0.5f, z, p);
    return fmaf((float)ex, 0.693147180559945f, f + p);
}

// exact 2^{-exponent(Z)} scale (pure ALU)
__device__ __forceinline__ float pow2_inv_scale(float Z) {
    int eb = (__float_as_int(Z) >> 23) & 0xFF;
    return __int_as_float((254 - eb) << 23);
}

// block reduction into g_F (all threads of block must call)
__device__ __forceinline__ void block_add_F(float v) {
    #pragma unroll
    for (int o = 16; o; o >>= 1) v += __shfl_down_sync(0xffffffffu, v, o);
    __shared__ float sh[32];
    int lane = threadIdx.x & 31, w = threadIdx.x >> 5;
    if (lane == 0) sh[w] = v;
    __syncthreads();
    if (w == 0) {
        int nw = (blockDim.x + 31) >> 5;
        float s = (lane < nw) ? sh[lane] : 0.0f;
        #pragma unroll
        for (int o = 16; o; o >>= 1) s += __shfl_down_sync(0xffffffffu, s, o);
        if (lane == 0) atomicAdd(&g_F, (double)s);
    }
}

// ---------------------------------------------------------------------------
// Setup: linearize potentials, init messages, zero F
// ---------------------------------------------------------------------------
__global__ void k_setup_plaq(const float4* __restrict__ lpp, int P4) {
    int i = blockIdx.x * blockDim.x + threadIdx.x;
    if (i == 0) g_F = 0.0;
    if (i >= P4) return;
    float4 v = lpp[i];
    float4 e = make_float4(__expf(v.x), __expf(v.y), __expf(v.z), __expf(v.w));
    g_phiP[i] = e;
    g_M[0][i] = make_float4(0.25f, 0.25f, 0.25f, 0.25f);
}

__global__ void k_setup_edge(const float4* __restrict__ lpe, int E) {
    int i = blockIdx.x * blockDim.x + threadIdx.x;
    if (i >= E) return;
    float4 v = lpe[i];
    g_phiE[i] = make_float4(__expf(v.x), __expf(v.y), __expf(v.z), __expf(v.w));
}

// ---------------------------------------------------------------------------
// Cavity gather: N_s = phi_edge_lin * (other parent's message, or 1)
//   slot 0: top edge h(pi,pj)    other = plaq(pi-1,pj)  slot 1
//   slot 1: bottom h(pi+1,pj)    other = plaq(pi+1,pj)  slot 0
//   slot 2: left v(pi,pj)        other = plaq(pi,pj-1)  slot 3
//   slot 3: right v(pi,pj+1)     other = plaq(pi,pj+1)  slot 2
// ---------------------------------------------------------------------------
__device__ __forceinline__ void gather_cavity(
    const float4* __restrict__ Min, int n, int pi, int pj, int p,
    float n0[4], float n1[4], float n2[4], float n3[4])
{
    int nm1 = n - 1;
    int nH = n * nm1;
    float4 N0 = g_phiE[p];                      // e0 = pi*nm1+pj = p
    float4 N1 = g_phiE[p + nm1];                // e1
    float4 N2 = g_phiE[nH + pi * n + pj];       // e2
    float4 N3 = g_phiE[nH + pi * n + pj + 1];   // e3
    if (pi > 0)       { float4 m = Min[(p - nm1) * 4 + 1]; N0.x *= m.x; N0.y *= m.y; N0.z *= m.z; N0.w *= m.w; }
    if (pi < nm1 - 1) { float4 m = Min[(p + nm1) * 4 + 0]; N1.x *= m.x; N1.y *= m.y; N1.z *= m.z; N1.w *= m.w; }
    if (pj > 0)       { float4 m = Min[(p - 1)   * 4 + 3]; N2.x *= m.x; N2.y *= m.y; N2.z *= m.z; N2.w *= m.w; }
    if (pj < nm1 - 1) { float4 m = Min[(p + 1)   * 4 + 2]; N3.x *= m.x; N3.y *= m.y; N3.z *= m.z; N3.w *= m.w; }
    n0[0] = N0.x; n0[1] = N0.y; n0[2] = N0.z; n0[3] = N0.w;
    n1[0] = N1.x; n1[1] = N1.y; n1[2] = N1.z; n1[3] = N1.w;
    n2[0] = N2.x; n2[1] = N2.y; n2[2] = N2.z; n2[3] = N2.w;
    n3[0] = N3.x; n3[1] = N3.y; n3[2] = N3.z; n3[3] = N3.w;
}

__device__ __forceinline__ void load_phi(int p, float Phi[16]) {
    float4 q;
    q = g_phiP[p * 4 + 0]; Phi[0]  = q.x; Phi[1]  = q.y; Phi[2]  = q.z; Phi[3]  = q.w;
    q = g_phiP[p * 4 + 1]; Phi[4]  = q.x; Phi[5]  = q.y; Phi[6]  = q.z; Phi[7]  = q.w;
    q = g_phiP[p * 4 + 2]; Phi[8]  = q.x; Phi[9]  = q.y; Phi[10] = q.z; Phi[11] = q.w;
    q = g_phiP[p * 4 + 3]; Phi[12] = q.x; Phi[13] = q.y; Phi[14] = q.z; Phi[15] = q.w;
}

// ---------------------------------------------------------------------------
// One BP iteration (division-free leave-one-out sums + pow2 normalization)
// ---------------------------------------------------------------------------
__global__ void k_iter(int src, int n) {
    int nm1 = n - 1;
    int pj = blockIdx.x * blockDim.x + threadIdx.x;
    int pi = blockIdx.y;
    if (pj >= nm1) return;
    int p = pi * nm1 + pj;

    const float4* Min = g_M[src];
    float4* Mout = g_M[src ^ 1];

    float n0[4], n1[4], n2[4], n3[4];
    gather_cavity(Min, n, pi, pj, p, n0, n1, n2, n3);
    float Phi[16];
    load_phi(p, Phi);

    float u0[4] = {0, 0, 0, 0}, u1[4] = {0, 0, 0, 0};
    float u2[4] = {0, 0, 0, 0}, u3[4] = {0, 0, 0, 0};
    #pragma unroll
    for (int a = 0; a < 2; a++)
    #pragma unroll
    for (int b = 0; b < 2; b++)
    #pragma unroll
    for (int c = 0; c < 2; c++)
    #pragma unroll
    for (int d = 0; d < 2; d++) {
        int idx = a * 8 + b * 4 + c * 2 + d;
        float ph = Phi[idx];
        float va = n0[a * 2 + b], vb = n1[c * 2 + d];
        float vc = n2[a * 2 + c], vd = n3[b * 2 + d];
        float q1 = ph * vc * vd;                 // Φ·N2·N3
        u0[a * 2 + b] = fmaf(q1, vb, u0[a * 2 + b]);
        u1[c * 2 + d] = fmaf(q1, va, u1[c * 2 + d]);
        float q2 = ph * va * vb;                 // Φ·N0·N1
        u2[a * 2 + c] = fmaf(q2, vd, u2[a * 2 + c]);
        u3[b * 2 + d] = fmaf(q2, vc, u3[b * 2 + d]);
    }

    {
        float Z = (u0[0] + u0[1]) + (u0[2] + u0[3]); float s = pow2_inv_scale(Z);
        Mout[p * 4 + 0] = make_float4(u0[0] * s, u0[1] * s, u0[2] * s, u0[3] * s);
    }
    {
        float Z = (u1[0] + u1[1]) + (u1[2] + u1[3]); float s = pow2_inv_scale(Z);
        Mout[p * 4 + 1] = make_float4(u1[0] * s, u1[1] * s, u1[2] * s, u1[3] * s);
    }
    {
        float Z = (u2[0] + u2[1]) + (u2[2] + u2[3]); float s = pow2_inv_scale(Z);
        Mout[p * 4 + 2] = make_float4(u2[0] * s, u2[1] * s, u2[2] * s, u2[3] * s);
    }
    {
        float Z = (u3[0] + u3[1]) + (u3[2] + u3[3]); float s = pow2_inv_scale(Z);
        Mout[p * 4 + 3] = make_float4(u3[0] * s, u3[1] * s, u3[2] * s, u3[3] * s);
    }
}

// ---------------------------------------------------------------------------
// Final per-edge: binary marginals b_e + interior-edge F term (c_e = -1)
// b_e ∝ phi_edge_lin * M_parent0 * M_parent1
// term = Σ b·log(M0·M1) − log(Z)   (scales cancel exactly)
// ---------------------------------------------------------------------------
__global__ void k_edge(int src, int n, float* __restrict__ out) {
    int e = blockIdx.x * blockDim.x + threadIdx.x;
    int nm1 = n - 1, nH = n * nm1, E = 2 * nH;
    float fterm = 0.0f;
    if (e < E) {
        const float4* M = g_M[src];
        int p0 = -1, s0 = 0, p1 = -1, s1 = 0;
        if (e < nH) {
            int hi = e / nm1; int hj = e - hi * nm1;
            if (hi < nm1) { p0 = hi * nm1 + hj; s0 = 0; }
            if (hi > 0)   { p1 = (hi - 1) * nm1 + hj; s1 = 1; }
        } else {
            int t = e - nH; int vi = t / n; int vj = t - vi * n;
            if (vj < nm1) { p0 = vi * nm1 + vj; s0 = 2; }
            if (vj > 0)   { p1 = vi * nm1 + vj - 1; s1 = 3; }
        }
        float4 pe = g_phiE[e];
        float mx = 1.f, my = 1.f, mz = 1.f, mw = 1.f;
        if (p0 >= 0) { float4 m = M[p0 * 4 + s0]; mx *= m.x; my *= m.y; mz *= m.z; mw *= m.w; }
        if (p1 >= 0) { float4 m = M[p1 * 4 + s1]; mx *= m.x; my *= m.y; mz *= m.z; mw *= m.w; }
        float tx = pe.x * mx, ty = pe.y * my, tz = pe.z * mz, tw = pe.w * mw;
        float Z = (tx + ty) + (tz + tw);
        float inv = __fdividef(1.0f, Z);
        float bx = tx * inv, by = ty * inv, bz = tz * inv, bw = tw * inv;
        int base = 1 + 2 * n * n + e * 4;
        out[base + 0] = bx; out[base + 1] = by; out[base + 2] = bz; out[base + 3] = bw;
        if (p0 >= 0 && p1 >= 0) {
            float l = bx * fast_logf(mx) + by * fast_logf(my)
                    + bz * fast_logf(mz) + bw * fast_logf(mw) - fast_logf(Z);
            fterm = -l;                       // c_e = 1 - 2 = -1
        }
    }
    block_add_F(fterm);
}

// ---------------------------------------------------------------------------
// Final per-plaquette F term: Σ b_p·(log_b_p − log_phi_plaq)
//   = (Σ_s Σ_x T_s[x]·log N_s[x]) / ΣE − log(ΣE)   (scales cancel exactly)
// ---------------------------------------------------------------------------
__global__ void k_plaq_final(int src, int n) {
    int nm1 = n - 1;
    int pj = blockIdx.x * blockDim.x + threadIdx.x;
    int pi = blockIdx.y;
    float term = 0.0f;
    if (pj < nm1) {
        int p = pi * nm1 + pj;
        const float4* Min = g_M[src];
        float n0[4], n1[4], n2[4], n3[4];
        gather_cavity(Min, n, pi, pj, p, n0, n1, n2, n3);
        float Phi[16];
        load_phi(p, Phi);

        float t0[4] = {0, 0, 0, 0}, t1[4] = {0, 0, 0, 0};
        float t2[4] = {0, 0, 0, 0}, t3[4] = {0, 0, 0, 0};
        #pragma unroll
        for (int a = 0; a < 2; a++)
        #pragma unroll
        for (int b = 0; b < 2; b++)
        #pragma unroll
        for (int c = 0; c < 2; c++)
        #pragma unroll
        for (int d = 0; d < 2; d++) {
            int idx = a * 8 + b * 4 + c * 2 + d;
            float ev = Phi[idx] * n0[a * 2 + b] * n1[c * 2 + d]
                                * n2[a * 2 + c] * n3[b * 2 + d];
            t0[a * 2 + b] += ev; t1[c * 2 + d] += ev;
            t2[a * 2 + c] += ev; t3[b * 2 + d] += ev;
        }
        float sumE = (t0[0] + t0[1]) + (t0[2] + t0[3]);
        float acc = 0.0f;
        #pragma unroll
        for (int x = 0; x < 4; x++) {
            acc = fmaf(t0[x], fast_logf(n0[x]), acc);
            acc = fmaf(t1[x], fast_logf(n1[x]), acc);
            acc = fmaf(t2[x], fast_logf(n2[x]), acc);
            acc = fmaf(t3[x], fast_logf(n3[x]), acc);
        }
        term = __fdividef(acc, sumE) - fast_logf(sumE);
    }
    block_add_F(term);
}

// ---------------------------------------------------------------------------
// Unary marginals: gather ≤4 incident edges' b_e from out (deterministic, no atomics)
// ---------------------------------------------------------------------------
__global__ void k_node(float* __restrict__ out, int n) {
    int j = blockIdx.x * blockDim.x + threadIdx.x;
    int i = blockIdx.y;
    if (j >= n) return;
    int nm1 = n - 1, nH = n * nm1;
    const float* B = out + 1 + 2 * n * n;
    float s0 = 0.f, s1 = 0.f; int deg = 0;
    if (j < nm1) { const float* b = B + (i * nm1 + j) * 4;        s0 += b[0] + b[1]; s1 += b[2] + b[3]; deg++; } // h-edge, node is var0 -> pa
    if (j > 0)   { const float* b = B + (i * nm1 + j - 1) * 4;    s0 += b[0] + b[2]; s1 += b[1] + b[3]; deg++; } // h-edge, var1 -> pb
    if (i < nm1) { const float* b = B + (nH + i * n + j) * 4;     s0 += b[0] + b[1]; s1 += b[2] + b[3]; deg++; } // v-edge, var0 -> pa
    if (i > 0)   { const float* b = B + (nH + (i - 1) * n + j) * 4; s0 += b[0] + b[2]; s1 += b[1] + b[3]; deg++; } // v-edge, var1 -> pb
    float invd = __fdividef(1.0f, (float)deg);
    int v = i * n + j;
    out[1 + v * 2 + 0] = s0 * invd;
    out[1 + v * 2 + 1] = s1 * invd;
}

__global__ void k_write_F(float* __restrict__ out) {
    if (threadIdx.x == 0 && blockIdx.x == 0) out[0] = (float)(-g_F);
}

// ---------------------------------------------------------------------------
extern "C" void kernel_launch(void* const* d_in, const int* in_sizes, int n_in,
                              void* d_out, int out_size) {
    const float* log_phi_plaq = (const float*)d_in[0];
    const float* log_phi_edge = (const float*)d_in[1];
    // d_in[2..6] (index arrays) are implied by grid regularity — never loaded.

    int P = in_sizes[0] / 16;
    int E = in_sizes[1] / 4;
    int nm1 = (int)lrint(sqrt((double)P));
    int n = nm1 + 1;
    (void)E; (void)n_in; (void)out_size;
    float* out = (float*)d_out;

    const int NITERS = 5;

    int P4 = P * 4;
    k_setup_plaq<<<(P4 + 255) / 256, 256>>>((const float4*)log_phi_plaq, P4);
    k_setup_edge<<<(E + 255) / 256, 256>>>((const float4*)log_phi_edge, E);

    dim3 bs(256);
    dim3 gr((nm1 + 255) / 256, nm1);
    int src = 0;
    for (int it = 0; it < NITERS; ++it) {
        k_iter<<<gr, bs>>>(src, n);
        src ^= 1;
    }

    k_edge<<<(E + 255) / 256, 256>>>(src, n, out);
    k_plaq_final<<<gr, bs>>>(src, n);
    k_node<<<dim3((n + 255) / 256, n), 256>>>(out, n);
    k_write_F<<<1, 32>>>(out);
}

// round 2
// speedup vs baseline: 1.2213x; 1.2213x over previous
#include <cuda_runtime.h>
#include <math.h>

// n=512 grid (runtime-derived, statically sized for max 512).
#define MAXNM1 511
#define MAXSP  (MAXNM1 + 2)
#define MAXSP2 (MAXSP * MAXSP)
#define MAXP   (MAXNM1 * MAXNM1)
#define MAXE   (2 * (MAXNM1 + 1) * MAXNM1)

// Messages as padded SoA planes: g_M[buf][slot][(pi+1)*sp + (pj+1)]
// Pads (border ring) are 1.0f => boundary cavity = phiE * 1, branch-free.
__device__ float4 g_M[2][4][MAXSP2];
__device__ float4 g_phiP[4][MAXP];   // plane k holds plaq states 4k..4k+3
__device__ float4 g_phiE[MAXE];      // exp(log_phi_edge)
__device__ double g_F;

// ---------------------------------------------------------------------------
__device__ __forceinline__ float fast_logf(float x) {
    int ix = __float_as_int(x);
    int ex = (ix >> 23) - 127;
    float m = __int_as_float((ix & 0x007FFFFF) | 0x3F800000);
    if (m > 1.41421356f) { m *= 0.5f; ex += 1; }
    float f = m - 1.0f;
    float z = f * f;
    float p = 7.0376836292e-2f;
    p = fmaf(p, f, -1.1514610310e-1f);
    p = fmaf(p, f,  1.1676998740e-1f);
    p = fmaf(p, f, -1.2420140846e-1f);
    p = fmaf(p, f,  1.4249322787e-1f);
    p = fmaf(p, f, -1.6668057665e-1f);
    p = fmaf(p, f,  2.0000714765e-1f);
    p = fmaf(p, f, -2.4999993993e-1f);
    p = fmaf(p, f,  3.3333331174e-1f);
    p = p * z * f;
    p = fmaf(-0.5f, z, p);
    return fmaf((float)ex, 0.693147180559945f, f + p);
}

__device__ __forceinline__ float pow2_inv_scale(float Z) {
    int eb = (__float_as_int(Z) >> 23) & 0xFF;
    return __int_as_float((254 - eb) << 23);
}

__device__ __forceinline__ void block_add_F(float v) {
    #pragma unroll
    for (int o = 16; o; o >>= 1) v += __shfl_down_sync(0xffffffffu, v, o);
    __shared__ float sh[32];
    int lane = threadIdx.x & 31, w = threadIdx.x >> 5;
    if (lane == 0) sh[w] = v;
    __syncthreads();
    if (w == 0) {
        int nw = (blockDim.x + 31) >> 5;
        float s = (lane < nw) ? sh[lane] : 0.0f;
        #pragma unroll
        for (int o = 16; o; o >>= 1) s += __shfl_down_sync(0xffffffffu, s, o);
        if (lane == 0) atomicAdd(&g_F, (double)s);
    }
}

// ---------------------------------------------------------------------------
// Pads: border ring of all 8 planes = 1.0f; also zero F.
__global__ void k_pads(int sp) {
    int i = blockIdx.x * blockDim.x + threadIdx.x;
    int plane = blockIdx.y;  // 0..7 = buf*4+slot
    if (i == 0 && plane == 0) g_F = 0.0;
    if (i >= sp) return;
    float4 one = make_float4(1.f, 1.f, 1.f, 1.f);
    float4* Mp = g_M[plane >> 2][plane & 3];
    Mp[i] = one;
    Mp[(sp - 1) * sp + i] = one;
    Mp[i * sp] = one;
    Mp[i * sp + (sp - 1)] = one;
}

__global__ void k_setup_edge(const float4* __restrict__ lpe, int E) {
    int i = blockIdx.x * blockDim.x + threadIdx.x;
    if (i >= E) return;
    float4 v = lpe[i];
    g_phiE[i] = make_float4(__expf(v.x), __expf(v.y), __expf(v.z), __expf(v.w));
}

__global__ void k_setup_phiP(const float4* __restrict__ lpp, int P) {
    int p = blockIdx.x * blockDim.x + threadIdx.x;
    int k = blockIdx.y;
    if (p >= P) return;
    float4 v = __ldg(&lpp[p * 4 + k]);
    g_phiP[k][p] = make_float4(__expf(v.x), __expf(v.y), __expf(v.z), __expf(v.w));
}

// ---------------------------------------------------------------------------
// Cavity gather (branch-free via pads): N_s = phiE_s * raw neighbor message
__device__ __forceinline__ void gather_cavity(
    int src, int nm1, int pi, int pj, int p, int q, int sp, bool first,
    float n0[4], float n1[4], float n2[4], float n3[4])
{
    int n = nm1 + 1;
    int nH = n * nm1;
    float4 N0 = g_phiE[p];
    float4 N1 = g_phiE[p + nm1];
    int e2 = nH + pi * n + pj;
    float4 N2 = g_phiE[e2];
    float4 N3 = g_phiE[e2 + 1];
    if (!first) {
        const float4* __restrict__ in0 = g_M[src][0];
        const float4* __restrict__ in1 = g_M[src][1];
        const float4* __restrict__ in2 = g_M[src][2];
        const float4* __restrict__ in3 = g_M[src][3];
        float4 r0 = in1[q - sp];
        float4 r1 = in0[q + sp];
        float4 r2 = in3[q - 1];
        float4 r3 = in2[q + 1];
        N0.x *= r0.x; N0.y *= r0.y; N0.z *= r0.z; N0.w *= r0.w;
        N1.x *= r1.x; N1.y *= r1.y; N1.z *= r1.z; N1.w *= r1.w;
        N2.x *= r2.x; N2.y *= r2.y; N2.z *= r2.z; N2.w *= r2.w;
        N3.x *= r3.x; N3.y *= r3.y; N3.z *= r3.z; N3.w *= r3.w;
    }
    n0[0] = N0.x; n0[1] = N0.y; n0[2] = N0.z; n0[3] = N0.w;
    n1[0] = N1.x; n1[1] = N1.y; n1[2] = N1.z; n1[3] = N1.w;
    n2[0] = N2.x; n2[1] = N2.y; n2[2] = N2.z; n2[3] = N2.w;
    n3[0] = N3.x; n3[1] = N3.y; n3[2] = N3.z; n3[3] = N3.w;
}

__device__ __forceinline__ void load_phi(int p, float Phi[16]) {
    float4 q;
    q = g_phiP[0][p]; Phi[0]  = q.x; Phi[1]  = q.y; Phi[2]  = q.z; Phi[3]  = q.w;
    q = g_phiP[1][p]; Phi[4]  = q.x; Phi[5]  = q.y; Phi[6]  = q.z; Phi[7]  = q.w;
    q = g_phiP[2][p]; Phi[8]  = q.x; Phi[9]  = q.y; Phi[10] = q.z; Phi[11] = q.w;
    q = g_phiP[3][p]; Phi[12] = q.x; Phi[13] = q.y; Phi[14] = q.z; Phi[15] = q.w;
}

// ---------------------------------------------------------------------------
template<bool FIRST>
__global__ void k_iter(int src, int nm1) {
    int pj = blockIdx.x * blockDim.x + threadIdx.x;
    int pi = blockIdx.y;
    if (pj >= nm1) return;
    int sp = nm1 + 2;
    int p = pi * nm1 + pj;
    int q = (pi + 1) * sp + (pj + 1);

    float n0[4], n1[4], n2[4], n3[4];
    gather_cavity(src, nm1, pi, pj, p, q, sp, FIRST, n0, n1, n2, n3);
    float Phi[16];
    load_phi(p, Phi);

    float u0[4] = {0, 0, 0, 0}, u1[4] = {0, 0, 0, 0};
    float u2[4] = {0, 0, 0, 0}, u3[4] = {0, 0, 0, 0};
    #pragma unroll
    for (int a = 0; a < 2; a++)
    #pragma unroll
    for (int b = 0; b < 2; b++)
    #pragma unroll
    for (int c = 0; c < 2; c++)
    #pragma unroll
    for (int d = 0; d < 2; d++) {
        int idx = a * 8 + b * 4 + c * 2 + d;
        float ph = Phi[idx];
        float va = n0[a * 2 + b], vb = n1[c * 2 + d];
        float vc = n2[a * 2 + c], vd = n3[b * 2 + d];
        float q1 = ph * vc * vd;
        u0[a * 2 + b] = fmaf(q1, vb, u0[a * 2 + b]);
        u1[c * 2 + d] = fmaf(q1, va, u1[c * 2 + d]);
        float q2 = ph * va * vb;
        u2[a * 2 + c] = fmaf(q2, vd, u2[a * 2 + c]);
        u3[b * 2 + d] = fmaf(q2, vc, u3[b * 2 + d]);
    }

    int dst = src ^ 1;
    float4* __restrict__ o0 = g_M[dst][0];
    float4* __restrict__ o1 = g_M[dst][1];
    float4* __restrict__ o2 = g_M[dst][2];
    float4* __restrict__ o3 = g_M[dst][3];
    {
        float Z = (u0[0] + u0[1]) + (u0[2] + u0[3]); float s = pow2_inv_scale(Z);
        o0[q] = make_float4(u0[0] * s, u0[1] * s, u0[2] * s, u0[3] * s);
    }
    {
        float Z = (u1[0] + u1[1]) + (u1[2] + u1[3]); float s = pow2_inv_scale(Z);
        o1[q] = make_float4(u1[0] * s, u1[1] * s, u1[2] * s, u1[3] * s);
    }
    {
        float Z = (u2[0] + u2[1]) + (u2[2] + u2[3]); float s = pow2_inv_scale(Z);
        o2[q] = make_float4(u2[0] * s, u2[1] * s, u2[2] * s, u2[3] * s);
    }
    {
        float Z = (u3[0] + u3[1]) + (u3[2] + u3[3]); float s = pow2_inv_scale(Z);
        o3[q] = make_float4(u3[0] * s, u3[1] * s, u3[2] * s, u3[3] * s);
    }
}

// ---------------------------------------------------------------------------
__global__ void k_plaq_final(int src, int nm1) {
    int pj = blockIdx.x * blockDim.x + threadIdx.x;
    int pi = blockIdx.y;
    float term = 0.0f;
    if (pj < nm1) {
        int sp = nm1 + 2;
        int p = pi * nm1 + pj;
        int q = (pi + 1) * sp + (pj + 1);
        float n0[4], n1[4], n2[4], n3[4];
        gather_cavity(src, nm1, pi, pj, p, q, sp, false, n0, n1, n2, n3);
        float Phi[16];
        load_phi(p, Phi);

        float t0[4] = {0, 0, 0, 0}, t1[4] = {0, 0, 0, 0};
        float t2[4] = {0, 0, 0, 0}, t3[4] = {0, 0, 0, 0};
        #pragma unroll
        for (int a = 0; a < 2; a++)
        #pragma unroll
        for (int b = 0; b < 2; b++)
        #pragma unroll
        for (int c = 0; c < 2; c++)
        #pragma unroll
        for (int d = 0; d < 2; d++) {
            int idx = a * 8 + b * 4 + c * 2 + d;
            float ev = Phi[idx] * n0[a * 2 + b] * n1[c * 2 + d]
                                * n2[a * 2 + c] * n3[b * 2 + d];
            t0[a * 2 + b] += ev; t1[c * 2 + d] += ev;
            t2[a * 2 + c] += ev; t3[b * 2 + d] += ev;
        }
        float sumE = (t0[0] + t0[1]) + (t0[2] + t0[3]);
        float acc = 0.0f;
        #pragma unroll
        for (int x = 0; x < 4; x++) {
            acc = fmaf(t0[x], fast_logf(n0[x]), acc);
            acc = fmaf(t1[x], fast_logf(n1[x]), acc);
            acc = fmaf(t2[x], fast_logf(n2[x]), acc);
            acc = fmaf(t3[x], fast_logf(n3[x]), acc);
        }
        term = __fdividef(acc, sumE) - fast_logf(sumE);
    }
    block_add_F(term);
}

// ---------------------------------------------------------------------------
// Horizontal edges: e = hi*nm1 + hj, hi in [0,n), hj in [0,nm1)
__global__ void k_edge_h(int src, int nm1, const float4* __restrict__ lpe,
                         float* __restrict__ out) {
    int hj = blockIdx.x * blockDim.x + threadIdx.x;
    int hi = blockIdx.y;
    int n = nm1 + 1, sp = nm1 + 2;
    float fterm = 0.0f;
    if (hj < nm1) {
        int e = hi * nm1 + hj;
        float4 m0 = g_M[src][0][(hi + 1) * sp + hj + 1]; // parent below (pad=1 if hi==nm1)
        float4 m1 = g_M[src][1][hi * sp + hj + 1];       // parent above (pad=1 if hi==0)
        float4 pe = g_phiE[e];
        float tx = pe.x * m0.x * m1.x, ty = pe.y * m0.y * m1.y;
        float tz = pe.z * m0.z * m1.z, tw = pe.w * m0.w * m1.w;
        float Z = (tx + ty) + (tz + tw);
        float inv = __fdividef(1.0f, Z);
        float bx = tx * inv, by = ty * inv, bz = tz * inv, bw = tw * inv;
        int base = 1 + 2 * n * n + e * 4;
        out[base + 0] = bx; out[base + 1] = by; out[base + 2] = bz; out[base + 3] = bw;
        if (hi > 0 && hi < nm1) {
            float4 lp = __ldg(&lpe[e]);
            float l = bx * (fast_logf(tx) - lp.x) + by * (fast_logf(ty) - lp.y)
                    + bz * (fast_logf(tz) - lp.z) + bw * (fast_logf(tw) - lp.w)
                    - fast_logf(Z);
            fterm = -l;
        }
    }
    block_add_F(fterm);
}

// Vertical edges: e = nH + vi*n + vj, vi in [0,nm1), vj in [0,n)
__global__ void k_edge_v(int src, int nm1, const float4* __restrict__ lpe,
                         float* __restrict__ out) {
    int vj = blockIdx.x * blockDim.x + threadIdx.x;
    int vi = blockIdx.y;
    int n = nm1 + 1, sp = nm1 + 2, nH = n * nm1;
    float fterm = 0.0f;
    if (vj < n) {
        int e = nH + vi * n + vj;
        float4 m0 = g_M[src][2][(vi + 1) * sp + vj + 1]; // parent right (pad=1 if vj==nm1)
        float4 m1 = g_M[src][3][(vi + 1) * sp + vj];     // parent left  (pad=1 if vj==0)
        float4 pe = g_phiE[e];
        float tx = pe.x * m0.x * m1.x, ty = pe.y * m0.y * m1.y;
        float tz = pe.z * m0.z * m1.z, tw = pe.w * m0.w * m1.w;
        float Z = (tx + ty) + (tz + tw);
        float inv = __fdividef(1.0f, Z);
        float bx = tx * inv, by = ty * inv, bz = tz * inv, bw = tw * inv;
        int base = 1 + 2 * n * n + e * 4;
        out[base + 0] = bx; out[base + 1] = by; out[base + 2] = bz; out[base + 3] = bw;
        if (vj > 0 && vj < nm1) {
            float4 lp = __ldg(&lpe[e]);
            float l = bx * (fast_logf(tx) - lp.x) + by * (fast_logf(ty) - lp.y)
                    + bz * (fast_logf(tz) - lp.z) + bw * (fast_logf(tw) - lp.w)
                    - fast_logf(Z);
            fterm = -l;
        }
    }
    block_add_F(fterm);
}

// ---------------------------------------------------------------------------
__global__ void k_node(float* __restrict__ out, int n) {
    int j = blockIdx.x * blockDim.x + threadIdx.x;
    int i = blockIdx.y;
    if (j >= n) return;
    int nm1 = n - 1, nH = n * nm1;
    const float* B = out + 1 + 2 * n * n;
    float s0 = 0.f, s1 = 0.f; int deg = 0;
    if (j < nm1) { const float* b = B + (i * nm1 + j) * 4;          s0 += b[0] + b[1]; s1 += b[2] + b[3]; deg++; }
    if (j > 0)   { const float* b = B + (i * nm1 + j - 1) * 4;      s0 += b[0] + b[2]; s1 += b[1] + b[3]; deg++; }
    if (i < nm1) { const float* b = B + (nH + i * n + j) * 4;       s0 += b[0] + b[1]; s1 += b[2] + b[3]; deg++; }
    if (i > 0)   { const float* b = B + (nH + (i - 1) * n + j) * 4; s0 += b[0] + b[2]; s1 += b[1] + b[3]; deg++; }
    float invd = __fdividef(1.0f, (float)deg);
    int v = i * n + j;
    out[1 + v * 2 + 0] = s0 * invd;
    out[1 + v * 2 + 1] = s1 * invd;
}

__global__ void k_write_F(float* __restrict__ out) {
    if (threadIdx.x == 0 && blockIdx.x == 0) out[0] = (float)(-g_F);
}

// ---------------------------------------------------------------------------
extern "C" void kernel_launch(void* const* d_in, const int* in_sizes, int n_in,
                              void* d_out, int out_size) {
    const float* log_phi_plaq = (const float*)d_in[0];
    const float* log_phi_edge = (const float*)d_in[1];

    int P = in_sizes[0] / 16;
    int E = in_sizes[1] / 4;
    int nm1 = (int)lrint(sqrt((double)P));
    int n = nm1 + 1;
    int sp = nm1 + 2;
    (void)n_in; (void)out_size;
    float* out = (float*)d_out;

    const int NITERS = 5;

    k_pads<<<dim3((sp + 127) / 128, 8), 128>>>(sp);
    k_setup_edge<<<(E + 255) / 256, 256>>>((const float4*)log_phi_edge, E);
    k_setup_phiP<<<dim3((P + 255) / 256, 4), 256>>>((const float4*)log_phi_plaq, P);

    dim3 bs(128);
    dim3 gr((nm1 + 127) / 128, nm1);
    int src = 0;
    k_iter<true><<<gr, bs>>>(src, nm1);   // reads nothing from g_M
    src ^= 1;
    for (int it = 1; it < NITERS; ++it) {
        k_iter<false><<<gr, bs>>>(src, nm1);
        src ^= 1;
    }

    k_edge_h<<<dim3((nm1 + 127) / 128, n), 128>>>(src, nm1, (const float4*)log_phi_edge, out);
    k_edge_v<<<dim3((n + 127) / 128, nm1), 128>>>(src, nm1, (const float4*)log_phi_edge, out);
    k_plaq_final<<<gr, bs>>>(src, nm1);
    k_node<<<dim3((n + 127) / 128, n), 128>>>(out, n);
    k_write_F<<<1, 32>>>(out);
}